// round 9
// baseline (speedup 1.0000x reference)
#include <cuda_runtime.h>

#define DFEAT 128
#define DF4   (DFEAT / 4)     // 32 float4 per node row
#define NMAX  50048
#define EMAX  800000

// Scratch in __device__ globals, referenced ONLY from device code.
// Feature buffers are float4 arrays -> guaranteed 16B alignment.
__device__ int    g_cnt[NMAX];
__device__ int    g_cursor[NMAX];
__device__ int    g_rowptr[NMAX + 1];
__device__ int    g_col[EMAX];
__device__ float  g_invdeg[NMAX];                    // scalar access only
__device__ float4 g_agg[(size_t)NMAX * DF4];
__device__ float4 g_h1 [(size_t)NMAX * DF4];
__device__ float4 g_h2 [(size_t)NMAX * DF4];

// ---------------------------------------------------------------- CSR build
__global__ void zero_cnt_kernel(int n) {
    int i = blockIdx.x * blockDim.x + threadIdx.x;
    if (i < n) { g_cnt[i] = 0; g_cursor[i] = 0; }
}

// edge_index is INT32 (JAX x64 disabled: jnp.int64 silently -> int32).
__global__ void count_kernel(const int* __restrict__ dst, int E) {
    int e = blockIdx.x * blockDim.x + threadIdx.x;
    if (e < E) atomicAdd(&g_cnt[dst[e]], 1);
}

__global__ void invdeg_kernel(int n) {
    int i = blockIdx.x * blockDim.x + threadIdx.x;
    if (i < n) g_invdeg[i] = 1.0f / (float)max(g_cnt[i], 1);
}

__global__ __launch_bounds__(1024)
void scan_kernel(int n) {
    __shared__ int partial[1024];
    const int t = threadIdx.x;
    const int per = (n + 1023) / 1024;
    const int start = t * per;
    const int end   = min(start + per, n);

    int s = 0;
    for (int i = start; i < end; i++) s += g_cnt[i];
    partial[t] = s;
    __syncthreads();

    for (int off = 1; off < 1024; off <<= 1) {
        int v = (t >= off) ? partial[t - off] : 0;
        __syncthreads();
        partial[t] += v;
        __syncthreads();
    }

    int run = (t == 0) ? 0 : partial[t - 1];
    for (int i = start; i < end; i++) { g_rowptr[i] = run; run += g_cnt[i]; }
    if (t == 1023) g_rowptr[n] = partial[1023];
}

__global__ void fill_kernel(const int* __restrict__ src,
                            const int* __restrict__ dst, int E) {
    int e = blockIdx.x * blockDim.x + threadIdx.x;
    if (e >= E) return;
    int d = dst[e];
    int pos = atomicAdd(&g_cursor[d], 1);
    g_col[g_rowptr[d] + pos] = src[e];
}

// ---------------------------------------------------------------- aggregation
// One warp per node, CSR walk, no float atomics. Each lane owns one float4
// (128 feats / 32 lanes); feature table (~25.6MB) is L2-resident, so the
// gathers are coalesced 512B L2 hits. Writes pre-scaled mean into g_agg;
// every node is covered, so no zero-fill needed.
__global__ __launch_bounds__(256)
void aggregate_csr(const float4* __restrict__ x4, int layer, int N) {
    const float4* h4 = (layer == 0) ? x4 : (layer == 1) ? g_h1 : g_h2;

    int node = blockIdx.x * (blockDim.x >> 5) + (threadIdx.x >> 5);
    int lane = threadIdx.x & 31;
    if (node >= N) return;

    int beg = g_rowptr[node], end = g_rowptr[node + 1];
    float4 acc = make_float4(0.f, 0.f, 0.f, 0.f);

    for (int i0 = beg; i0 < end; i0 += 32) {
        int nbr = (i0 + lane < end) ? g_col[i0 + lane] : 0;
        int cntc = min(32, end - i0);
        for (int j = 0; j < cntc; j++) {
            int s = __shfl_sync(0xffffffffu, nbr, j);
            float4 v = h4[(size_t)s * DF4 + lane];
            acc.x += v.x; acc.y += v.y; acc.z += v.z; acc.w += v.w;
        }
    }
    float id = g_invdeg[node];
    acc.x *= id; acc.y *= id; acc.z *= id; acc.w *= id;
    g_agg[(size_t)node * DF4 + lane] = acc;
}

// ---------------------------------------------------------------- fused SAGE GEMM
// out[n,j] = relu?( sum_k agg[n,k]*Wl[j,k] + bl[j] + sum_k h[n,k]*Wr[j,k] )
// g_agg already mean-scaled. 256 thr/block, per-thread 4-row x 8-col tile.
// Weights K-tiled in 32-deep slices -> 32KB static shared. Buffers selected
// device-side from the layer index.
#define KTILE 32

template<int DOUT, bool RELU>
__global__ __launch_bounds__(256)
void sage_gemm(const float4* __restrict__ x4,
               const float* __restrict__ Wl, const float* __restrict__ bl,
               const float* __restrict__ Wr,
               float4* __restrict__ dout4, int layer, int N) {
    const float4* hin4 = (layer == 0) ? x4 : (layer == 1) ? g_h1 : g_h2;
    float4*       out4 = (layer == 0) ? g_h1 : (layer == 1) ? g_h2 : dout4;
    const float4* agg4 = g_agg;

    constexpr int CG   = DOUT / 8;     // column groups of 8
    constexpr int RG   = 256 / CG;     // row groups
    constexpr int ROWS = RG * 4;       // rows per block
    constexpr int D4   = DOUT / 4;

    __shared__ float sWl[KTILE][DOUT]; // sWl[k][j] = Wl[j][kt+k]
    __shared__ float sWr[KTILE][DOUT];

    const int colg = threadIdx.x % CG;
    const int rowg = threadIdx.x / CG;
    const int row0 = blockIdx.x * ROWS + rowg * 4;
    const int col0 = colg * 8;

    int rr[4];
#pragma unroll
    for (int r = 0; r < 4; r++) rr[r] = min(row0 + r, N - 1);  // clamped loads

    float acc[4][8];
#pragma unroll
    for (int r = 0; r < 4; r++)
#pragma unroll
        for (int c = 0; c < 8; c++) acc[r][c] = 0.f;

    for (int kt = 0; kt < DFEAT; kt += KTILE) {
        for (int i = threadIdx.x; i < DOUT * KTILE; i += 256) {
            int j = i / KTILE, k = i % KTILE;
            sWl[k][j] = Wl[j * DFEAT + kt + k];
            sWr[k][j] = Wr[j * DFEAT + kt + k];
        }
        __syncthreads();

        for (int k0 = 0; k0 < KTILE; k0 += 4) {
            float av[4][4], hv[4][4];
#pragma unroll
            for (int r = 0; r < 4; r++) {
                float4 ta = agg4[(size_t)rr[r] * DF4 + (kt + k0) / 4];
                float4 th = hin4[(size_t)rr[r] * DF4 + (kt + k0) / 4];
                av[r][0] = ta.x; av[r][1] = ta.y; av[r][2] = ta.z; av[r][3] = ta.w;
                hv[r][0] = th.x; hv[r][1] = th.y; hv[r][2] = th.z; hv[r][3] = th.w;
            }
#pragma unroll
            for (int kk = 0; kk < 4; kk++) {
                float wl[8], wr[8];
#pragma unroll
                for (int c = 0; c < 8; c++) {
                    wl[c] = sWl[k0 + kk][col0 + c];
                    wr[c] = sWr[k0 + kk][col0 + c];
                }
#pragma unroll
                for (int r = 0; r < 4; r++) {
                    float a = av[r][kk], hh = hv[r][kk];
#pragma unroll
                    for (int c = 0; c < 8; c++)
                        acc[r][c] += a * wl[c] + hh * wr[c];
                }
            }
        }
        __syncthreads();
    }

#pragma unroll
    for (int r = 0; r < 4; r++) {
        int row = row0 + r;
        if (row < N) {
            float v[8];
#pragma unroll
            for (int c = 0; c < 8; c++) {
                float t = acc[r][c] + bl[col0 + c];
                v[c] = RELU ? fmaxf(t, 0.f) : t;
            }
            out4[(size_t)row * D4 + col0 / 4]     = make_float4(v[0], v[1], v[2], v[3]);
            out4[(size_t)row * D4 + col0 / 4 + 1] = make_float4(v[4], v[5], v[6], v[7]);
        }
    }
}

// ---------------------------------------------------------------- launch
// ONLY kernel launches; only harness-provided pointers cross the boundary.
extern "C" void kernel_launch(void* const* d_in, const int* in_sizes, int n_in,
                              void* d_out, int out_size) {
    const float4* x4 = (const float4*)d_in[0];
    const int*    ei = (const int*)d_in[1];          // int32! (JAX x64 off)
    const float *Wl0 = (const float*)d_in[2], *bl0 = (const float*)d_in[3],
                *Wr0 = (const float*)d_in[4];
    const float *Wl1 = (const float*)d_in[5], *bl1 = (const float*)d_in[6],
                *Wr1 = (const float*)d_in[7];
    const float *Wl2 = (const float*)d_in[8], *bl2 = (const float*)d_in[9],
                *Wr2 = (const float*)d_in[10];

    const int N = in_sizes[0] / DFEAT;
    const int E = in_sizes[1] / 2;
    const int* src = ei;
    const int* dst = ei + E;

    const int TB = 256;
    const int eBlocks = (E + TB - 1) / TB;
    const int nBlocks = (N + TB - 1) / TB;
    const int aggBlocks = (N + 7) / 8;   // 8 warps/block, 1 node/warp

    // ---- CSR build (shared across all 3 layers) ----
    zero_cnt_kernel<<<nBlocks, TB>>>(N);
    count_kernel<<<eBlocks, TB>>>(dst, E);
    invdeg_kernel<<<nBlocks, TB>>>(N);
    scan_kernel<<<1, 1024>>>(N);
    fill_kernel<<<eBlocks, TB>>>(src, dst, E);

    // ---- layer 0: x -> h1 (relu) ----
    aggregate_csr<<<aggBlocks, TB>>>(x4, 0, N);
    sage_gemm<128, true><<<(N + 63) / 64, 256>>>(x4, Wl0, bl0, Wr0, nullptr, 0, N);

    // ---- layer 1: h1 -> h2 (relu) ----
    aggregate_csr<<<aggBlocks, TB>>>(x4, 1, N);
    sage_gemm<128, true><<<(N + 63) / 64, 256>>>(x4, Wl1, bl1, Wr1, nullptr, 1, N);

    // ---- layer 2: h2 -> out (no relu) ----
    aggregate_csr<<<aggBlocks, TB>>>(x4, 2, N);
    sage_gemm<64, false><<<(N + 127) / 128, 256>>>(x4, Wl2, bl2, Wr2,
                                                   (float4*)d_out, 2, N);
}

// round 10
// speedup vs baseline: 1.0705x; 1.0705x over previous
#include <cuda_runtime.h>

#define DFEAT 128
#define DF4   (DFEAT / 4)
#define NMAX  50048
#define EMAX  800000
#define SCAN_TB 256
#define NBMAX   ((NMAX + SCAN_TB - 1) / SCAN_TB)   // 196

typedef unsigned long long ull;

#define FMA_F32X2(d, a, b, c) \
    asm("fma.rn.f32x2 %0, %1, %2, %3;" : "=l"(d) : "l"(a), "l"(b), "l"(c))
#define PACK_F32X2(out, lo, hi) \
    asm("mov.b64 %0, {%1, %2};" : "=l"(out) : "f"(lo), "f"(hi))
#define UNPACK_F32X2(lo, hi, in) \
    asm("mov.b64 {%0, %1}, %2;" : "=f"(lo), "=f"(hi) : "l"(in))

// Scratch in __device__ globals, device-side references only.
__device__ int    g_cnt[NMAX];
__device__ int    g_cursor[NMAX];
__device__ int    g_rowptr[NMAX + 1];
__device__ int    g_col[EMAX];
__device__ int    g_bsum[NBMAX + 32];
__device__ int    g_boff[NBMAX + 32];
__device__ float  g_invdeg[NMAX];
__device__ float4 g_agg[(size_t)NMAX * DF4];
__device__ float4 g_h1 [(size_t)NMAX * DF4];
__device__ float4 g_h2 [(size_t)NMAX * DF4];

// ---------------------------------------------------------------- CSR build
__global__ void zero_cnt_kernel(int n) {
    int i = blockIdx.x * blockDim.x + threadIdx.x;
    if (i < n) { g_cnt[i] = 0; g_cursor[i] = 0; }
}

// edge_index is INT32 (JAX x64 disabled).
__global__ void count_kernel(const int* __restrict__ dst, int E) {
    int e = blockIdx.x * blockDim.x + threadIdx.x;
    if (e < E) atomicAdd(&g_cnt[dst[e]], 1);
}

__global__ void invdeg_kernel(int n) {
    int i = blockIdx.x * blockDim.x + threadIdx.x;
    if (i < n) g_invdeg[i] = 1.0f / (float)max(g_cnt[i], 1);
}

// ---- parallel scan, phase 1: per-block sums (full chip, ~2us) ----
__global__ __launch_bounds__(SCAN_TB)
void block_sum_kernel(int n) {
    __shared__ int ws[SCAN_TB / 32];
    int i = blockIdx.x * SCAN_TB + threadIdx.x;
    int v = (i < n) ? g_cnt[i] : 0;
#pragma unroll
    for (int o = 16; o > 0; o >>= 1) v += __shfl_down_sync(0xffffffffu, v, o);
    if ((threadIdx.x & 31) == 0) ws[threadIdx.x >> 5] = v;
    __syncthreads();
    if (threadIdx.x < SCAN_TB / 32) {
        int s = ws[threadIdx.x];
#pragma unroll
        for (int o = SCAN_TB / 64; o > 0; o >>= 1)
            s += __shfl_down_sync(0xffffffffu, s, o);
        if (threadIdx.x == 0) g_bsum[blockIdx.x] = s;
    }
}

// ---- phase 2: exclusive scan of <=256 block sums in one block ----
__global__ __launch_bounds__(SCAN_TB)
void scan_bsum_kernel(int nb, int n) {
    __shared__ int sm[SCAN_TB];
    int t = threadIdx.x;
    int v = (t < nb) ? g_bsum[t] : 0;
    sm[t] = v;
    __syncthreads();
#pragma unroll
    for (int o = 1; o < SCAN_TB; o <<= 1) {
        int u = (t >= o) ? sm[t - o] : 0;
        __syncthreads();
        sm[t] += u;
        __syncthreads();
    }
    if (t < nb) g_boff[t] = sm[t] - v;          // exclusive
    if (t == SCAN_TB - 1) g_rowptr[n] = sm[SCAN_TB - 1];
}

// ---- phase 3: per-block exclusive rescan + global offset ----
__global__ __launch_bounds__(SCAN_TB)
void rowptr_kernel(int n) {
    __shared__ int sm[SCAN_TB];
    int t = threadIdx.x;
    int i = blockIdx.x * SCAN_TB + t;
    int v = (i < n) ? g_cnt[i] : 0;
    sm[t] = v;
    __syncthreads();
#pragma unroll
    for (int o = 1; o < SCAN_TB; o <<= 1) {
        int u = (t >= o) ? sm[t - o] : 0;
        __syncthreads();
        sm[t] += u;
        __syncthreads();
    }
    if (i < n) g_rowptr[i] = g_boff[blockIdx.x] + sm[t] - v;
}

__global__ void fill_kernel(const int* __restrict__ src,
                            const int* __restrict__ dst, int E) {
    int e = blockIdx.x * blockDim.x + threadIdx.x;
    if (e >= E) return;
    int d = dst[e];
    int pos = atomicAdd(&g_cursor[d], 1);
    g_col[g_rowptr[d] + pos] = src[e];
}

// ---------------------------------------------------------------- aggregation
// One warp per node, CSR walk, no float atomics. Feature table ~25.6MB ->
// L2-resident; gathers are coalesced 512B reads. Writes pre-scaled mean.
__global__ __launch_bounds__(256)
void aggregate_csr(const float4* __restrict__ x4, int layer, int N) {
    const float4* h4 = (layer == 0) ? x4 : (layer == 1) ? g_h1 : g_h2;

    int node = blockIdx.x * (blockDim.x >> 5) + (threadIdx.x >> 5);
    int lane = threadIdx.x & 31;
    if (node >= N) return;

    int beg = g_rowptr[node], end = g_rowptr[node + 1];
    float4 acc = make_float4(0.f, 0.f, 0.f, 0.f);

    for (int i0 = beg; i0 < end; i0 += 32) {
        int nbr = (i0 + lane < end) ? g_col[i0 + lane] : 0;
        int cntc = min(32, end - i0);
        for (int j = 0; j < cntc; j++) {
            int s = __shfl_sync(0xffffffffu, nbr, j);
            float4 v = h4[(size_t)s * DF4 + lane];
            acc.x += v.x; acc.y += v.y; acc.z += v.z; acc.w += v.w;
        }
    }
    float id = g_invdeg[node];
    acc.x *= id; acc.y *= id; acc.z *= id; acc.w *= id;
    g_agg[(size_t)node * DF4 + lane] = acc;
}

// ---------------------------------------------------------------- fused SAGE GEMM
// out[n,j] = relu?( agg[n,:]·Wl[j,:] + bl[j] + h[n,:]·Wr[j,:] )
// Inner product in PACKED f32x2 (FFMA2): halves FMA instruction count.
#define KTILE 32

template<int DOUT, bool RELU>
__global__ __launch_bounds__(256)
void sage_gemm(const float4* __restrict__ x4,
               const float* __restrict__ Wl, const float* __restrict__ bl,
               const float* __restrict__ Wr,
               float4* __restrict__ dout4, int layer, int N) {
    const float4* hin4 = (layer == 0) ? x4 : (layer == 1) ? g_h1 : g_h2;
    float4*       out4 = (layer == 0) ? g_h1 : (layer == 1) ? g_h2 : dout4;
    const float4* agg4 = g_agg;

    constexpr int CG   = DOUT / 8;
    constexpr int RG   = 256 / CG;
    constexpr int ROWS = RG * 4;
    constexpr int D4   = DOUT / 4;

    __shared__ float sWl[KTILE][DOUT];   // sWl[k][j] = Wl[j][kt+k]
    __shared__ float sWr[KTILE][DOUT];

    const int colg = threadIdx.x % CG;
    const int rowg = threadIdx.x / CG;
    const int row0 = blockIdx.x * ROWS + rowg * 4;
    const int col0 = colg * 8;           // 8 cols -> 4 packed pairs (8B aligned)

    int rr[4];
#pragma unroll
    for (int r = 0; r < 4; r++) rr[r] = min(row0 + r, N - 1);

    ull acc2[4][4];
#pragma unroll
    for (int r = 0; r < 4; r++)
#pragma unroll
        for (int c = 0; c < 4; c++) acc2[r][c] = 0ull;

    for (int kt = 0; kt < DFEAT; kt += KTILE) {
        for (int i = threadIdx.x; i < DOUT * KTILE; i += 256) {
            int j = i / KTILE, k = i % KTILE;
            sWl[k][j] = Wl[j * DFEAT + kt + k];
            sWr[k][j] = Wr[j * DFEAT + kt + k];
        }
        __syncthreads();

        for (int k0 = 0; k0 < KTILE; k0 += 4) {
            float av[4][4], hv[4][4];
#pragma unroll
            for (int r = 0; r < 4; r++) {
                float4 ta = agg4[(size_t)rr[r] * DF4 + (kt + k0) / 4];
                float4 th = hin4[(size_t)rr[r] * DF4 + (kt + k0) / 4];
                av[r][0] = ta.x; av[r][1] = ta.y; av[r][2] = ta.z; av[r][3] = ta.w;
                hv[r][0] = th.x; hv[r][1] = th.y; hv[r][2] = th.z; hv[r][3] = th.w;
            }
#pragma unroll
            for (int kk = 0; kk < 4; kk++) {
                ull wl2[4], wr2[4];
#pragma unroll
                for (int c = 0; c < 4; c++) {   // 8B LDS of a float pair
                    wl2[c] = *(const ull*)&sWl[k0 + kk][col0 + 2 * c];
                    wr2[c] = *(const ull*)&sWr[k0 + kk][col0 + 2 * c];
                }
#pragma unroll
                for (int r = 0; r < 4; r++) {
                    ull a2, h2;
                    PACK_F32X2(a2, av[r][kk], av[r][kk]);
                    PACK_F32X2(h2, hv[r][kk], hv[r][kk]);
#pragma unroll
                    for (int c = 0; c < 4; c++) {
                        FMA_F32X2(acc2[r][c], a2, wl2[c], acc2[r][c]);
                        FMA_F32X2(acc2[r][c], h2, wr2[c], acc2[r][c]);
                    }
                }
            }
        }
        __syncthreads();
    }

#pragma unroll
    for (int r = 0; r < 4; r++) {
        int row = row0 + r;
        if (row < N) {
            float v[8];
#pragma unroll
            for (int c = 0; c < 4; c++)
                UNPACK_F32X2(v[2 * c], v[2 * c + 1], acc2[r][c]);
#pragma unroll
            for (int c = 0; c < 8; c++) {
                float t = v[c] + bl[col0 + c];
                v[c] = RELU ? fmaxf(t, 0.f) : t;
            }
            out4[(size_t)row * D4 + col0 / 4]     = make_float4(v[0], v[1], v[2], v[3]);
            out4[(size_t)row * D4 + col0 / 4 + 1] = make_float4(v[4], v[5], v[6], v[7]);
        }
    }
}

// ---------------------------------------------------------------- launch
extern "C" void kernel_launch(void* const* d_in, const int* in_sizes, int n_in,
                              void* d_out, int out_size) {
    const float4* x4 = (const float4*)d_in[0];
    const int*    ei = (const int*)d_in[1];
    const float *Wl0 = (const float*)d_in[2], *bl0 = (const float*)d_in[3],
                *Wr0 = (const float*)d_in[4];
    const float *Wl1 = (const float*)d_in[5], *bl1 = (const float*)d_in[6],
                *Wr1 = (const float*)d_in[7];
    const float *Wl2 = (const float*)d_in[8], *bl2 = (const float*)d_in[9],
                *Wr2 = (const float*)d_in[10];

    const int N = in_sizes[0] / DFEAT;
    const int E = in_sizes[1] / 2;
    const int* src = ei;
    const int* dst = ei + E;

    const int TB = 256;
    const int eBlocks = (E + TB - 1) / TB;
    const int nBlocks = (N + TB - 1) / TB;
    const int sBlocks = (N + SCAN_TB - 1) / SCAN_TB;   // <= 196 -> 1-block phase2
    const int aggBlocks = (N + 7) / 8;

    // ---- CSR build (shared across all 3 layers) ----
    zero_cnt_kernel<<<nBlocks, TB>>>(N);
    count_kernel<<<eBlocks, TB>>>(dst, E);
    invdeg_kernel<<<nBlocks, TB>>>(N);
    block_sum_kernel<<<sBlocks, SCAN_TB>>>(N);
    scan_bsum_kernel<<<1, SCAN_TB>>>(sBlocks, N);
    rowptr_kernel<<<sBlocks, SCAN_TB>>>(N);
    fill_kernel<<<eBlocks, TB>>>(src, dst, E);

    // ---- layer 0: x -> h1 (relu) ----
    aggregate_csr<<<aggBlocks, TB>>>(x4, 0, N);
    sage_gemm<128, true><<<(N + 63) / 64, 256>>>(x4, Wl0, bl0, Wr0, nullptr, 0, N);

    // ---- layer 1: h1 -> h2 (relu) ----
    aggregate_csr<<<aggBlocks, TB>>>(x4, 1, N);
    sage_gemm<128, true><<<(N + 63) / 64, 256>>>(x4, Wl1, bl1, Wr1, nullptr, 1, N);

    // ---- layer 2: h2 -> out (no relu) ----
    aggregate_csr<<<aggBlocks, TB>>>(x4, 2, N);
    sage_gemm<64, false><<<(N + 127) / 128, 256>>>(x4, Wl2, bl2, Wr2,
                                                   (float4*)d_out, 2, N);
}

// round 13
// speedup vs baseline: 2.0061x; 1.8740x over previous
#include <cuda_runtime.h>
#include <cstdint>

#define DFEAT 128
#define DF4   (DFEAT / 4)
#define NMAX  50048
#define EMAX  800000
#define SCAN_TB 256
#define NBMAX   ((NMAX + SCAN_TB - 1) / SCAN_TB)

// Scratch in __device__ globals, device-side references only.
__device__ int    g_cnt[NMAX];
__device__ int    g_cursor[NMAX];
__device__ int    g_rowptr[NMAX + 1];
__device__ int    g_col[EMAX];
__device__ int    g_bsum[NBMAX + 32];
__device__ int    g_boff[NBMAX + 32];
__device__ float  g_invdeg[NMAX];
__device__ float4 g_agg[(size_t)NMAX * DF4];
__device__ float4 g_h1 [(size_t)NMAX * DF4];
__device__ float4 g_h2 [(size_t)NMAX * DF4];

// ---------------------------------------------------------------- CSR build
__global__ void zero_cnt_kernel(int n) {
    int i = blockIdx.x * blockDim.x + threadIdx.x;
    if (i < n) { g_cnt[i] = 0; g_cursor[i] = 0; }
}

__global__ void count_kernel(const int* __restrict__ dst, int E) {
    int e = blockIdx.x * blockDim.x + threadIdx.x;
    if (e < E) atomicAdd(&g_cnt[dst[e]], 1);
}

__global__ void invdeg_kernel(int n) {
    int i = blockIdx.x * blockDim.x + threadIdx.x;
    if (i < n) g_invdeg[i] = 1.0f / (float)max(g_cnt[i], 1);
}

__global__ __launch_bounds__(SCAN_TB)
void block_sum_kernel(int n) {
    __shared__ int ws[SCAN_TB / 32];
    int i = blockIdx.x * SCAN_TB + threadIdx.x;
    int v = (i < n) ? g_cnt[i] : 0;
#pragma unroll
    for (int o = 16; o > 0; o >>= 1) v += __shfl_down_sync(0xffffffffu, v, o);
    if ((threadIdx.x & 31) == 0) ws[threadIdx.x >> 5] = v;
    __syncthreads();
    if (threadIdx.x < SCAN_TB / 32) {
        int s = ws[threadIdx.x];
#pragma unroll
        for (int o = SCAN_TB / 64; o > 0; o >>= 1)
            s += __shfl_down_sync(0xffffffffu, s, o);
        if (threadIdx.x == 0) g_bsum[blockIdx.x] = s;
    }
}

__global__ __launch_bounds__(SCAN_TB)
void scan_bsum_kernel(int nb, int n) {
    __shared__ int sm[SCAN_TB];
    int t = threadIdx.x;
    int v = (t < nb) ? g_bsum[t] : 0;
    sm[t] = v;
    __syncthreads();
#pragma unroll
    for (int o = 1; o < SCAN_TB; o <<= 1) {
        int u = (t >= o) ? sm[t - o] : 0;
        __syncthreads();
        sm[t] += u;
        __syncthreads();
    }
    if (t < nb) g_boff[t] = sm[t] - v;
    if (t == SCAN_TB - 1) g_rowptr[n] = sm[SCAN_TB - 1];
}

__global__ __launch_bounds__(SCAN_TB)
void rowptr_kernel(int n) {
    __shared__ int sm[SCAN_TB];
    int t = threadIdx.x;
    int i = blockIdx.x * SCAN_TB + t;
    int v = (i < n) ? g_cnt[i] : 0;
    sm[t] = v;
    __syncthreads();
#pragma unroll
    for (int o = 1; o < SCAN_TB; o <<= 1) {
        int u = (t >= o) ? sm[t - o] : 0;
        __syncthreads();
        sm[t] += u;
        __syncthreads();
    }
    if (i < n) g_rowptr[i] = g_boff[blockIdx.x] + sm[t] - v;
}

__global__ void fill_kernel(const int* __restrict__ src,
                            const int* __restrict__ dst, int E) {
    int e = blockIdx.x * blockDim.x + threadIdx.x;
    if (e >= E) return;
    int d = dst[e];
    int pos = atomicAdd(&g_cursor[d], 1);
    g_col[g_rowptr[d] + pos] = src[e];
}

// ---------------------------------------------------------------- aggregation
__global__ __launch_bounds__(256)
void aggregate_csr(const float4* __restrict__ x4, int layer, int N) {
    const float4* h4 = (layer == 0) ? x4 : (layer == 1) ? g_h1 : g_h2;

    int node = blockIdx.x * (blockDim.x >> 5) + (threadIdx.x >> 5);
    int lane = threadIdx.x & 31;
    if (node >= N) return;

    int beg = g_rowptr[node], end = g_rowptr[node + 1];
    float4 acc = make_float4(0.f, 0.f, 0.f, 0.f);

    for (int i0 = beg; i0 < end; i0 += 32) {
        int nbr = (i0 + lane < end) ? g_col[i0 + lane] : 0;
        int cntc = min(32, end - i0);
        for (int j = 0; j < cntc; j++) {
            int s = __shfl_sync(0xffffffffu, nbr, j);
            float4 v = h4[(size_t)s * DF4 + lane];
            acc.x += v.x; acc.y += v.y; acc.z += v.z; acc.w += v.w;
        }
    }
    float id = g_invdeg[node];
    acc.x *= id; acc.y *= id; acc.z *= id; acc.w *= id;
    g_agg[(size_t)node * DF4 + lane] = acc;
}

// ---------------------------------------------------------------- tensor-core GEMM
// out = relu?( agg @ Wl^T + bl + h @ Wr^T ), fp32 via 3xTF32 HMMA.
// mma.sync.aligned.m16n8k8.row.col.f32.tf32.tf32.f32 fragment layout:
//   A: a0(g,tg) a1(g+8,tg) a2(g,tg+4) a3(g+8,tg+4)
//   B: b0(k=tg,n=g) b1(k=tg+4,n=g)
//   C: c0(g,2tg) c1(g,2tg+1) c2(g+8,2tg) c3(g+8,2tg+1)
__device__ __forceinline__ uint32_t f2tf32(float x) {
    uint32_t r; asm("cvt.rna.tf32.f32 %0, %1;" : "=r"(r) : "f"(x)); return r;
}
__device__ __forceinline__ void tf32_split(float x, uint32_t& hi, uint32_t& lo) {
    hi = f2tf32(x);
    lo = f2tf32(x - __uint_as_float(hi));
}
__device__ __forceinline__ void mma8(float* c, uint32_t a0, uint32_t a1,
                                     uint32_t a2, uint32_t a3,
                                     uint32_t b0, uint32_t b1) {
    asm("mma.sync.aligned.m16n8k8.row.col.f32.tf32.tf32.f32 "
        "{%0,%1,%2,%3}, {%4,%5,%6,%7}, {%8,%9}, {%0,%1,%2,%3};"
        : "+f"(c[0]), "+f"(c[1]), "+f"(c[2]), "+f"(c[3])
        : "r"(a0), "r"(a1), "r"(a2), "r"(a3), "r"(b0), "r"(b1));
}

template<int DOUT, bool RELU>
__global__ __launch_bounds__(256)
void sage_gemm_tc(const float4* __restrict__ x4,
                  const float* __restrict__ Wl, const float* __restrict__ bl,
                  const float* __restrict__ Wr,
                  float4* __restrict__ dout4, int layer, int N) {
    const float* hin = (const float*)((layer == 0) ? x4 : (layer == 1) ? g_h1 : g_h2);
    float*       out = (float*)((layer == 0) ? g_h1 : (layer == 1) ? g_h2 : dout4);
    const float* agg = (const float*)g_agg;

    constexpr int NW_N = 2;            // warps along N
    constexpr int WN   = DOUT / NW_N;  // cols per warp
    constexpr int NT   = WN / 8;       // n8 tiles per warp

    const int warp = threadIdx.x >> 5;
    const int lane = threadIdx.x & 31;
    const int g    = lane >> 2;
    const int tg   = lane & 3;

    const int wm = warp / NW_N;                       // 0..3
    const int wn = warp % NW_N;                       // 0..1
    const int rowbase = blockIdx.x * 128 + wm * 32;   // two m16 tiles
    const int colbase = wn * WN;

    float acc[2][NT][4];
#pragma unroll
    for (int m = 0; m < 2; m++)
#pragma unroll
        for (int t = 0; t < NT; t++)
#pragma unroll
            for (int i = 0; i < 4; i++) acc[m][t][i] = 0.f;

#pragma unroll
    for (int p = 0; p < 2; p++) {
        const float* A = p ? hin : agg;
        const float* B = p ? Wr  : Wl;

        for (int k0 = 0; k0 < DFEAT; k0 += 8) {
            uint32_t ahi[2][4], alo[2][4];
#pragma unroll
            for (int m = 0; m < 2; m++) {
                int ra = min(rowbase + m * 16 + g, N - 1);
                int rb = min(rowbase + m * 16 + g + 8, N - 1);
                float v0 = A[(size_t)ra * DFEAT + k0 + tg];
                float v1 = A[(size_t)rb * DFEAT + k0 + tg];
                float v2 = A[(size_t)ra * DFEAT + k0 + tg + 4];
                float v3 = A[(size_t)rb * DFEAT + k0 + tg + 4];
                tf32_split(v0, ahi[m][0], alo[m][0]);
                tf32_split(v1, ahi[m][1], alo[m][1]);
                tf32_split(v2, ahi[m][2], alo[m][2]);
                tf32_split(v3, ahi[m][3], alo[m][3]);
            }
#pragma unroll
            for (int t = 0; t < NT; t++) {
                int n0 = colbase + t * 8;
                float w0 = B[(size_t)(n0 + g) * DFEAT + k0 + tg];
                float w1 = B[(size_t)(n0 + g) * DFEAT + k0 + tg + 4];
                uint32_t b0h, b0l, b1h, b1l;
                tf32_split(w0, b0h, b0l);
                tf32_split(w1, b1h, b1l);
#pragma unroll
                for (int m = 0; m < 2; m++) {
                    mma8(acc[m][t], ahi[m][0], ahi[m][1], ahi[m][2], ahi[m][3], b0h, b1h);
                    mma8(acc[m][t], ahi[m][0], ahi[m][1], ahi[m][2], ahi[m][3], b0l, b1l);
                    mma8(acc[m][t], alo[m][0], alo[m][1], alo[m][2], alo[m][3], b0h, b1h);
                }
            }
        }
    }

    // epilogue: bias (+relu), store float2 pairs
#pragma unroll
    for (int t = 0; t < NT; t++) {
        int c0 = colbase + t * 8 + 2 * tg;
        float bb0 = bl[c0], bb1 = bl[c0 + 1];
#pragma unroll
        for (int m = 0; m < 2; m++) {
            int r0 = rowbase + m * 16 + g;
            int r1 = r0 + 8;
            float2 v0 = make_float2(acc[m][t][0] + bb0, acc[m][t][1] + bb1);
            float2 v1 = make_float2(acc[m][t][2] + bb0, acc[m][t][3] + bb1);
            if (RELU) {
                v0.x = fmaxf(v0.x, 0.f); v0.y = fmaxf(v0.y, 0.f);
                v1.x = fmaxf(v1.x, 0.f); v1.y = fmaxf(v1.y, 0.f);
            }
            if (r0 < N) *(float2*)&out[(size_t)r0 * DOUT + c0] = v0;
            if (r1 < N) *(float2*)&out[(size_t)r1 * DOUT + c0] = v1;
        }
    }
}

// ---------------------------------------------------------------- launch
extern "C" void kernel_launch(void* const* d_in, const int* in_sizes, int n_in,
                              void* d_out, int out_size) {
    const float4* x4 = (const float4*)d_in[0];
    const int*    ei = (const int*)d_in[1];
    const float *Wl0 = (const float*)d_in[2], *bl0 = (const float*)d_in[3],
                *Wr0 = (const float*)d_in[4];
    const float *Wl1 = (const float*)d_in[5], *bl1 = (const float*)d_in[6],
                *Wr1 = (const float*)d_in[7];
    const float *Wl2 = (const float*)d_in[8], *bl2 = (const float*)d_in[9],
                *Wr2 = (const float*)d_in[10];

    const int N = in_sizes[0] / DFEAT;
    const int E = in_sizes[1] / 2;
    const int* src = ei;
    const int* dst = ei + E;

    const int TB = 256;
    const int eBlocks = (E + TB - 1) / TB;
    const int nBlocks = (N + TB - 1) / TB;
    const int sBlocks = (N + SCAN_TB - 1) / SCAN_TB;
    const int aggBlocks = (N + 7) / 8;
    const int gemmBlocks = (N + 127) / 128;

    // ---- CSR build (shared across all 3 layers) ----
    zero_cnt_kernel<<<nBlocks, TB>>>(N);
    count_kernel<<<eBlocks, TB>>>(dst, E);
    invdeg_kernel<<<nBlocks, TB>>>(N);
    block_sum_kernel<<<sBlocks, SCAN_TB>>>(N);
    scan_bsum_kernel<<<1, SCAN_TB>>>(sBlocks, N);
    rowptr_kernel<<<sBlocks, SCAN_TB>>>(N);
    fill_kernel<<<eBlocks, TB>>>(src, dst, E);

    // ---- layer 0: x -> h1 (relu) ----
    aggregate_csr<<<aggBlocks, TB>>>(x4, 0, N);
    sage_gemm_tc<128, true><<<gemmBlocks, 256>>>(x4, Wl0, bl0, Wr0, nullptr, 0, N);

    // ---- layer 1: h1 -> h2 (relu) ----
    aggregate_csr<<<aggBlocks, TB>>>(x4, 1, N);
    sage_gemm_tc<128, true><<<gemmBlocks, 256>>>(x4, Wl1, bl1, Wr1, nullptr, 1, N);

    // ---- layer 2: h2 -> out (no relu) ----
    aggregate_csr<<<aggBlocks, TB>>>(x4, 2, N);
    sage_gemm_tc<64, false><<<gemmBlocks, 256>>>(x4, Wl2, bl2, Wr2,
                                                 (float4*)d_out, 2, N);
}

// round 14
// speedup vs baseline: 2.0471x; 1.0205x over previous
#include <cuda_runtime.h>
#include <cstdint>

#define DFEAT 128
#define DF4   (DFEAT / 4)
#define NMAX  50048
#define EMAX  800000
#define SCAN_TB 256
#define NBMAX   ((NMAX + SCAN_TB - 1) / SCAN_TB)

// Scratch in __device__ globals, device-side references only.
__device__ int    g_cnt[NMAX];
__device__ int    g_cursor[NMAX];
__device__ int    g_rowptr[NMAX + 1];
__device__ int    g_col[EMAX];
__device__ int    g_bsum[NBMAX + 32];
__device__ int    g_boff[NBMAX + 32];
__device__ float  g_invdeg[NMAX];
__device__ float4 g_agg[(size_t)NMAX * DF4];
__device__ float4 g_h1 [(size_t)NMAX * DF4];
__device__ float4 g_h2 [(size_t)NMAX * DF4];

// ---------------------------------------------------------------- CSR build
__global__ void zero_cnt_kernel(int n) {
    int i = blockIdx.x * blockDim.x + threadIdx.x;
    if (i < n) g_cnt[i] = 0;
}

__global__ void count_kernel(const int* __restrict__ dst, int E) {
    int e = blockIdx.x * blockDim.x + threadIdx.x;
    if (e < E) atomicAdd(&g_cnt[dst[e]], 1);
}

__global__ __launch_bounds__(SCAN_TB)
void block_sum_kernel(int n) {
    __shared__ int ws[SCAN_TB / 32];
    int i = blockIdx.x * SCAN_TB + threadIdx.x;
    int v = (i < n) ? g_cnt[i] : 0;
#pragma unroll
    for (int o = 16; o > 0; o >>= 1) v += __shfl_down_sync(0xffffffffu, v, o);
    if ((threadIdx.x & 31) == 0) ws[threadIdx.x >> 5] = v;
    __syncthreads();
    if (threadIdx.x < SCAN_TB / 32) {
        int s = ws[threadIdx.x];
#pragma unroll
        for (int o = SCAN_TB / 64; o > 0; o >>= 1)
            s += __shfl_down_sync(0xffffffffu, s, o);
        if (threadIdx.x == 0) g_bsum[blockIdx.x] = s;
    }
}

__global__ __launch_bounds__(SCAN_TB)
void scan_bsum_kernel(int nb, int n) {
    __shared__ int sm[SCAN_TB];
    int t = threadIdx.x;
    int v = (t < nb) ? g_bsum[t] : 0;
    sm[t] = v;
    __syncthreads();
#pragma unroll
    for (int o = 1; o < SCAN_TB; o <<= 1) {
        int u = (t >= o) ? sm[t - o] : 0;
        __syncthreads();
        sm[t] += u;
        __syncthreads();
    }
    if (t < nb) g_boff[t] = sm[t] - v;
    if (t == SCAN_TB - 1) g_rowptr[n] = sm[SCAN_TB - 1];
}

// rowptr + invdeg + cursor-zero fused (all consume/cover the same index space).
__global__ __launch_bounds__(SCAN_TB)
void rowptr_kernel(int n) {
    __shared__ int sm[SCAN_TB];
    int t = threadIdx.x;
    int i = blockIdx.x * SCAN_TB + t;
    int v = (i < n) ? g_cnt[i] : 0;
    sm[t] = v;
    __syncthreads();
#pragma unroll
    for (int o = 1; o < SCAN_TB; o <<= 1) {
        int u = (t >= o) ? sm[t - o] : 0;
        __syncthreads();
        sm[t] += u;
        __syncthreads();
    }
    if (i < n) {
        g_rowptr[i] = g_boff[blockIdx.x] + sm[t] - v;
        g_invdeg[i] = 1.0f / (float)max(v, 1);
        g_cursor[i] = 0;
    }
}

__global__ void fill_kernel(const int* __restrict__ src,
                            const int* __restrict__ dst, int E) {
    int e = blockIdx.x * blockDim.x + threadIdx.x;
    if (e >= E) return;
    int d = dst[e];
    int pos = atomicAdd(&g_cursor[d], 1);
    g_col[g_rowptr[d] + pos] = src[e];
}

// ---------------------------------------------------------------- aggregation
// One warp per node. Full 32-edge chunks use a COMPILE-TIME trip count so
// ptxas front-batches the gathers (MLP >> 1); short dynamic tail for the rest.
__global__ __launch_bounds__(256)
void aggregate_csr(const float4* __restrict__ x4, int layer, int N) {
    const float4* h4 = (layer == 0) ? x4 : (layer == 1) ? g_h1 : g_h2;

    int node = blockIdx.x * (blockDim.x >> 5) + (threadIdx.x >> 5);
    int lane = threadIdx.x & 31;
    if (node >= N) return;

    int beg = g_rowptr[node], end = g_rowptr[node + 1];
    float id = g_invdeg[node];

    float4 acc0 = make_float4(0.f, 0.f, 0.f, 0.f);
    float4 acc1 = make_float4(0.f, 0.f, 0.f, 0.f);

    int i0 = beg;
    // full chunks: static unroll -> batched LDGs, two accumulator chains
    for (; i0 + 32 <= end; i0 += 32) {
        int nbr = g_col[i0 + lane];
#pragma unroll
        for (int j = 0; j < 32; j += 2) {
            int s0 = __shfl_sync(0xffffffffu, nbr, j);
            int s1 = __shfl_sync(0xffffffffu, nbr, j + 1);
            float4 v0 = h4[(size_t)s0 * DF4 + lane];
            float4 v1 = h4[(size_t)s1 * DF4 + lane];
            acc0.x += v0.x; acc0.y += v0.y; acc0.z += v0.z; acc0.w += v0.w;
            acc1.x += v1.x; acc1.y += v1.y; acc1.z += v1.z; acc1.w += v1.w;
        }
    }
    // tail (< 32 edges)
    if (i0 < end) {
        int nbr = (i0 + lane < end) ? g_col[i0 + lane] : 0;
        int cntc = end - i0;
        int j = 0;
        for (; j + 4 <= cntc; j += 4) {
            int s0 = __shfl_sync(0xffffffffu, nbr, j);
            int s1 = __shfl_sync(0xffffffffu, nbr, j + 1);
            int s2 = __shfl_sync(0xffffffffu, nbr, j + 2);
            int s3 = __shfl_sync(0xffffffffu, nbr, j + 3);
            float4 v0 = h4[(size_t)s0 * DF4 + lane];
            float4 v1 = h4[(size_t)s1 * DF4 + lane];
            float4 v2 = h4[(size_t)s2 * DF4 + lane];
            float4 v3 = h4[(size_t)s3 * DF4 + lane];
            acc0.x += v0.x; acc0.y += v0.y; acc0.z += v0.z; acc0.w += v0.w;
            acc1.x += v1.x; acc1.y += v1.y; acc1.z += v1.z; acc1.w += v1.w;
            acc0.x += v2.x; acc0.y += v2.y; acc0.z += v2.z; acc0.w += v2.w;
            acc1.x += v3.x; acc1.y += v3.y; acc1.z += v3.z; acc1.w += v3.w;
        }
        for (; j < cntc; j++) {
            int s = __shfl_sync(0xffffffffu, nbr, j);
            float4 v = h4[(size_t)s * DF4 + lane];
            acc0.x += v.x; acc0.y += v.y; acc0.z += v.z; acc0.w += v.w;
        }
    }

    float4 acc = make_float4((acc0.x + acc1.x) * id, (acc0.y + acc1.y) * id,
                             (acc0.z + acc1.z) * id, (acc0.w + acc1.w) * id);
    g_agg[(size_t)node * DF4 + lane] = acc;
}

// ---------------------------------------------------------------- tensor-core GEMM
// out = relu?( agg @ Wl^T + bl + h @ Wr^T ), fp32 via 3xTF32 HMMA.
__device__ __forceinline__ uint32_t f2tf32(float x) {
    uint32_t r; asm("cvt.rna.tf32.f32 %0, %1;" : "=r"(r) : "f"(x)); return r;
}
__device__ __forceinline__ void tf32_split(float x, uint32_t& hi, uint32_t& lo) {
    hi = f2tf32(x);
    lo = f2tf32(x - __uint_as_float(hi));
}
__device__ __forceinline__ void mma8(float* c, uint32_t a0, uint32_t a1,
                                     uint32_t a2, uint32_t a3,
                                     uint32_t b0, uint32_t b1) {
    asm("mma.sync.aligned.m16n8k8.row.col.f32.tf32.tf32.f32 "
        "{%0,%1,%2,%3}, {%4,%5,%6,%7}, {%8,%9}, {%0,%1,%2,%3};"
        : "+f"(c[0]), "+f"(c[1]), "+f"(c[2]), "+f"(c[3])
        : "r"(a0), "r"(a1), "r"(a2), "r"(a3), "r"(b0), "r"(b1));
}

template<int DOUT, bool RELU>
__global__ __launch_bounds__(256)
void sage_gemm_tc(const float4* __restrict__ x4,
                  const float* __restrict__ Wl, const float* __restrict__ bl,
                  const float* __restrict__ Wr,
                  float4* __restrict__ dout4, int layer, int N) {
    const float* hin = (const float*)((layer == 0) ? x4 : (layer == 1) ? g_h1 : g_h2);
    float*       out = (float*)((layer == 0) ? g_h1 : (layer == 1) ? g_h2 : dout4);
    const float* agg = (const float*)g_agg;

    constexpr int NW_N = 2;
    constexpr int WN   = DOUT / NW_N;
    constexpr int NT   = WN / 8;

    const int warp = threadIdx.x >> 5;
    const int lane = threadIdx.x & 31;
    const int g    = lane >> 2;
    const int tg   = lane & 3;

    const int wm = warp / NW_N;
    const int wn = warp % NW_N;
    const int rowbase = blockIdx.x * 128 + wm * 32;
    const int colbase = wn * WN;

    float acc[2][NT][4];
#pragma unroll
    for (int m = 0; m < 2; m++)
#pragma unroll
        for (int t = 0; t < NT; t++)
#pragma unroll
            for (int i = 0; i < 4; i++) acc[m][t][i] = 0.f;

#pragma unroll
    for (int p = 0; p < 2; p++) {
        const float* A = p ? hin : agg;
        const float* B = p ? Wr  : Wl;

        for (int k0 = 0; k0 < DFEAT; k0 += 8) {
            uint32_t ahi[2][4], alo[2][4];
#pragma unroll
            for (int m = 0; m < 2; m++) {
                int ra = min(rowbase + m * 16 + g, N - 1);
                int rb = min(rowbase + m * 16 + g + 8, N - 1);
                float v0 = A[(size_t)ra * DFEAT + k0 + tg];
                float v1 = A[(size_t)rb * DFEAT + k0 + tg];
                float v2 = A[(size_t)ra * DFEAT + k0 + tg + 4];
                float v3 = A[(size_t)rb * DFEAT + k0 + tg + 4];
                tf32_split(v0, ahi[m][0], alo[m][0]);
                tf32_split(v1, ahi[m][1], alo[m][1]);
                tf32_split(v2, ahi[m][2], alo[m][2]);
                tf32_split(v3, ahi[m][3], alo[m][3]);
            }
#pragma unroll
            for (int t = 0; t < NT; t++) {
                int n0 = colbase + t * 8;
                float w0 = B[(size_t)(n0 + g) * DFEAT + k0 + tg];
                float w1 = B[(size_t)(n0 + g) * DFEAT + k0 + tg + 4];
                uint32_t b0h, b0l, b1h, b1l;
                tf32_split(w0, b0h, b0l);
                tf32_split(w1, b1h, b1l);
#pragma unroll
                for (int m = 0; m < 2; m++) {
                    mma8(acc[m][t], ahi[m][0], ahi[m][1], ahi[m][2], ahi[m][3], b0h, b1h);
                    mma8(acc[m][t], ahi[m][0], ahi[m][1], ahi[m][2], ahi[m][3], b0l, b1l);
                    mma8(acc[m][t], alo[m][0], alo[m][1], alo[m][2], alo[m][3], b0h, b1h);
                }
            }
        }
    }

#pragma unroll
    for (int t = 0; t < NT; t++) {
        int c0 = colbase + t * 8 + 2 * tg;
        float bb0 = bl[c0], bb1 = bl[c0 + 1];
#pragma unroll
        for (int m = 0; m < 2; m++) {
            int r0 = rowbase + m * 16 + g;
            int r1 = r0 + 8;
            float2 v0 = make_float2(acc[m][t][0] + bb0, acc[m][t][1] + bb1);
            float2 v1 = make_float2(acc[m][t][2] + bb0, acc[m][t][3] + bb1);
            if (RELU) {
                v0.x = fmaxf(v0.x, 0.f); v0.y = fmaxf(v0.y, 0.f);
                v1.x = fmaxf(v1.x, 0.f); v1.y = fmaxf(v1.y, 0.f);
            }
            if (r0 < N) *(float2*)&out[(size_t)r0 * DOUT + c0] = v0;
            if (r1 < N) *(float2*)&out[(size_t)r1 * DOUT + c0] = v1;
        }
    }
}

// ---------------------------------------------------------------- launch
extern "C" void kernel_launch(void* const* d_in, const int* in_sizes, int n_in,
                              void* d_out, int out_size) {
    const float4* x4 = (const float4*)d_in[0];
    const int*    ei = (const int*)d_in[1];
    const float *Wl0 = (const float*)d_in[2], *bl0 = (const float*)d_in[3],
                *Wr0 = (const float*)d_in[4];
    const float *Wl1 = (const float*)d_in[5], *bl1 = (const float*)d_in[6],
                *Wr1 = (const float*)d_in[7];
    const float *Wl2 = (const float*)d_in[8], *bl2 = (const float*)d_in[9],
                *Wr2 = (const float*)d_in[10];

    const int N = in_sizes[0] / DFEAT;
    const int E = in_sizes[1] / 2;
    const int* src = ei;
    const int* dst = ei + E;

    const int TB = 256;
    const int eBlocks = (E + TB - 1) / TB;
    const int nBlocks = (N + TB - 1) / TB;
    const int sBlocks = (N + SCAN_TB - 1) / SCAN_TB;
    const int aggBlocks = (N + 7) / 8;
    const int gemmBlocks = (N + 127) / 128;

    // ---- CSR build (shared across all 3 layers) ----
    zero_cnt_kernel<<<nBlocks, TB>>>(N);
    count_kernel<<<eBlocks, TB>>>(dst, E);
    block_sum_kernel<<<sBlocks, SCAN_TB>>>(N);
    scan_bsum_kernel<<<1, SCAN_TB>>>(sBlocks, N);
    rowptr_kernel<<<sBlocks, SCAN_TB>>>(N);      // rowptr + invdeg + cursor=0
    fill_kernel<<<eBlocks, TB>>>(src, dst, E);

    // ---- layer 0: x -> h1 (relu) ----
    aggregate_csr<<<aggBlocks, TB>>>(x4, 0, N);
    sage_gemm_tc<128, true><<<gemmBlocks, 256>>>(x4, Wl0, bl0, Wr0, nullptr, 0, N);

    // ---- layer 1: h1 -> h2 (relu) ----
    aggregate_csr<<<aggBlocks, TB>>>(x4, 1, N);
    sage_gemm_tc<128, true><<<gemmBlocks, 256>>>(x4, Wl1, bl1, Wr1, nullptr, 1, N);

    // ---- layer 2: h2 -> out (no relu) ----
    aggregate_csr<<<aggBlocks, TB>>>(x4, 2, N);
    sage_gemm_tc<64, false><<<gemmBlocks, 256>>>(x4, Wl2, bl2, Wr2,
                                                 (float4*)d_out, 2, N);
}